// round 4
// baseline (speedup 1.0000x reference)
#include <cuda_runtime.h>
#include <math.h>
#include <stdint.h>

// ---------------- problem constants ----------------
#define BB   8
#define MM   1024
#define DD   768
#define NE   32
#define PE   32
#define KK   8
#define HH   2048
#define SS   1024            // N*P
#define TT   8192            // B*M

// ---------------- scratch (device globals; no allocs allowed) ----------------
__device__ float g_xn   [TT * DD];          // unweighted normalized x
__device__ float g_colinv[SS];              // scale / ||phi_col||
__device__ float g_part [32 * NE * DD];     // seg0 partials (sum xn)
__device__ float g_part2[32 * NE * DD];     // seg1 partials (sum |xn-mean|)
__device__ float g_cpart[32 * NE];
__device__ float g_mad  [NE * DD];
__device__ float g_W    [NE * DD];
__device__ float g_logits[TT * SS];         // logits, later overwritten by comb
__device__ float g_disp [TT * SS];
__device__ float g_rowmax[TT], g_rowsum[TT];
__device__ float g_colmax[BB * SS], g_colsum[BB * SS];
__device__ float g_xs [NE * (BB*PE) * DD];  // [n][b*32+p][d]
__device__ float g_h  [NE * (BB*PE) * HH];
__device__ float g_ys [NE * (BB*PE) * DD];

__device__ __forceinline__ float gelu_f(float v) {
    return 0.5f * v * (1.0f + erff(v * 0.70710678118654752440f));
}

__device__ __forceinline__ float tf32r(float x) {
    uint32_t r;
    asm("cvt.rna.tf32.f32 %0, %1;" : "=r"(r) : "f"(x));
    return __uint_as_float(r);
}

__device__ __forceinline__ void mma_tf32(float* c, const uint32_t* a,
                                         uint32_t b0, uint32_t b1) {
    asm volatile(
        "mma.sync.aligned.m16n8k8.row.col.f32.tf32.tf32.f32 "
        "{%0,%1,%2,%3}, {%4,%5,%6,%7}, {%8,%9}, {%0,%1,%2,%3};"
        : "+f"(c[0]), "+f"(c[1]), "+f"(c[2]), "+f"(c[3])
        : "r"(a[0]), "r"(a[1]), "r"(a[2]), "r"(a[3]), "r"(b0), "r"(b1));
}

// ---------------- launch 0: phi column inverse norms ----------------
__global__ void k_colinv(const float* __restrict__ phi, const float* __restrict__ scale) {
    int c = blockIdx.x * 256 + threadIdx.x;
    float ss = 0.f;
    for (int d = 0; d < DD; d++) { float v = phi[(size_t)d * SS + c]; ss += v * v; }
    g_colinv[c] = scale[0] / fmaxf(sqrtf(ss), 1e-12f);
}

// ---------------- launch 1: token L2 normalize ----------------
__global__ void k_norm_x(const float* __restrict__ x) {
    int t = blockIdx.x, tid = threadIdx.x;
    const float* xr = x + (size_t)t * DD;
    float v0 = xr[tid], v1 = xr[tid + 256], v2 = xr[tid + 512];
    __shared__ float red[256];
    red[tid] = v0*v0 + v1*v1 + v2*v2;
    __syncthreads();
    for (int o = 128; o; o >>= 1) { if (tid < o) red[tid] += red[tid+o]; __syncthreads(); }
    float inv = 1.0f / fmaxf(sqrtf(red[0]), 1e-12f);
    float* o = g_xn + (size_t)t * DD;
    o[tid] = v0*inv; o[tid+256] = v1*inv; o[tid+512] = v2*inv;
}

// ---------------- launch 2: segment sums of xn (deterministic) ----------------
__global__ void k_seg0(const int* __restrict__ ca) {
    __shared__ float acc[32][129];
    __shared__ float cnt[32];
    int tid = threadIdx.x;
    int tg = blockIdx.x, d0 = blockIdx.y * 128;
    for (int c = 0; c < 32; c++) acc[c][tid] = 0.f;
    if (tid < 32) cnt[tid] = 0.f;
    __syncthreads();
    int t0 = tg * 256;
    for (int tt = 0; tt < 256; tt++) {
        int t = t0 + tt;
        int c = ca[(size_t)t * KK];
        acc[c][tid] += g_xn[(size_t)t * DD + d0 + tid];
        if (blockIdx.y == 0 && tid == 0) cnt[c] += 1.f;
    }
    __syncthreads();
    for (int c = 0; c < 32; c++)
        g_part[((size_t)tg * 32 + c) * DD + d0 + tid] = acc[c][tid];
    if (blockIdx.y == 0 && tid < 32) g_cpart[tg * 32 + tid] = cnt[tid];
}

// ---------------- launch 3: seg of |xn - mean| with fused mean reduction ----------------
__global__ void k_seg1f(const int* __restrict__ ca) {
    __shared__ float acc[32][129];
    __shared__ float meanS[32][129];
    __shared__ float cn[32];
    int tid = threadIdx.x;
    int tg = blockIdx.x, d0 = blockIdx.y * 128;
    if (tid < 32) {
        float s = 0.f;
        for (int g = 0; g < 32; g++) s += g_cpart[g * 32 + tid];
        cn[tid] = s;
    }
    __syncthreads();
    for (int c = 0; c < 32; c++) {
        float s = 0.f;
        #pragma unroll 4
        for (int g = 0; g < 32; g++) s += g_part[((size_t)g * 32 + c) * DD + d0 + tid];
        meanS[c][tid] = cn[c] > 0.f ? s / cn[c] : 0.f;
        acc[c][tid] = 0.f;
    }
    __syncthreads();
    int t0 = tg * 256;
    for (int tt = 0; tt < 256; tt++) {
        int t = t0 + tt;
        int c = ca[(size_t)t * KK];
        float v = g_xn[(size_t)t * DD + d0 + tid];
        acc[c][tid] += fabsf(v - meanS[c][tid]);
    }
    __syncthreads();
    for (int c = 0; c < 32; c++)
        g_part2[((size_t)tg * 32 + c) * DD + d0 + tid] = acc[c][tid];
}

// ---------------- launch 4: fused mad-reduction + W clamp/renormalize ----------------
__global__ void k_Wf() {
    __shared__ float red[1024];
    __shared__ float cn[32];
    int tid = threadIdx.x;
    if (tid < 32) {
        float s = 0.f;
        for (int g = 0; g < 32; g++) s += g_cpart[g * 32 + tid];
        cn[tid] = s;
    }
    __syncthreads();
    for (int i = tid; i < NE * DD; i += 1024) {
        int c = i / DD, d = i % DD;
        float s = 0.f;
        for (int g = 0; g < 32; g++) s += g_part2[((size_t)g * 32 + c) * DD + d];
        g_mad[i] = cn[c] > 0.f ? s / cn[c] : 0.f;
    }
    __syncthreads();
    float l = 0.f;
    for (int i = tid; i < NE * DD; i += 1024) l += 1.0f / (g_mad[i] + 0.35f);
    red[tid] = l; __syncthreads();
    for (int o = 512; o; o >>= 1) { if (tid < o) red[tid] += red[tid+o]; __syncthreads(); }
    float top = 5.0f * red[0] / (float)(NE * DD);
    __syncthreads();
    float l2 = 0.f;
    for (int i = tid; i < NE * DD; i += 1024) l2 += fminf(1.0f / (g_mad[i] + 0.35f), top);
    red[tid] = l2; __syncthreads();
    for (int o = 512; o; o >>= 1) { if (tid < o) red[tid] += red[tid+o]; __syncthreads(); }
    float m2 = red[0] / (float)(NE * DD);
    __syncthreads();
    for (int i = tid; i < NE * DD; i += 1024)
        g_W[i] = fminf(1.0f / (g_mad[i] + 0.35f), top) / m2;
}

// ---------------- launch 5: split-tf32 logits GEMM (exactness-preserving) ----------------
// logits[8192,1024] = (xn*W)[8192,768] @ (phi*colinv)[768,1024]
// 3-term split: hi*hi + hi*lo + lo*hi; abs error ~1e-8 -> top-k ordering safe.
__global__ void __launch_bounds__(256, 2) gemm_logits(const float* __restrict__ phi,
                                                      const int* __restrict__ ca) {
    const int i0 = blockIdx.y * 128, j0 = blockIdx.x * 128;
    const int tid = threadIdx.x, lane = tid & 31, warp = tid >> 5;
    const int wmi = warp & 3, wni = warp >> 2;

    __shared__ float As[2][16][136];
    __shared__ float Bs[2][16][136];

    const int ar = tid >> 1, akq = (tid & 1) * 8;
    const int akk = tid >> 4, ac = (tid & 15) * 8;
    const int token = i0 + ar;
    const int cc = ca[(size_t)token * KK];
    const float* Wrow = g_W + (size_t)cc * DD;
    float ci[8];
    #pragma unroll
    for (int q = 0; q < 8; q++) ci[q] = g_colinv[j0 + ac + q];

    float acc[2][8][4];
    #pragma unroll
    for (int mf = 0; mf < 2; mf++)
        #pragma unroll
        for (int nf = 0; nf < 8; nf++)
            #pragma unroll
            for (int q = 0; q < 4; q++) acc[mf][nf][q] = 0.f;

    float4 ra0, ra1, rw0, rw1, rb0, rb1;

    auto loadg = [&](int k0) {
        const float* p = g_xn + (size_t)token * DD + k0 + akq;
        ra0 = *(const float4*)p; ra1 = *(const float4*)(p + 4);
        const float* w = Wrow + k0 + akq;
        rw0 = *(const float4*)w; rw1 = *(const float4*)(w + 4);
        const float* pb = phi + (size_t)(k0 + akk) * SS + j0 + ac;
        rb0 = *(const float4*)pb; rb1 = *(const float4*)(pb + 4);
    };

    auto stage = [&](int buf) {
        As[buf][akq+0][ar] = ra0.x * rw0.x;
        As[buf][akq+1][ar] = ra0.y * rw0.y;
        As[buf][akq+2][ar] = ra0.z * rw0.z;
        As[buf][akq+3][ar] = ra0.w * rw0.w;
        As[buf][akq+4][ar] = ra1.x * rw1.x;
        As[buf][akq+5][ar] = ra1.y * rw1.y;
        As[buf][akq+6][ar] = ra1.z * rw1.z;
        As[buf][akq+7][ar] = ra1.w * rw1.w;
        float* d = &Bs[buf][akk][ac];
        d[0] = rb0.x * ci[0]; d[1] = rb0.y * ci[1];
        d[2] = rb0.z * ci[2]; d[3] = rb0.w * ci[3];
        d[4] = rb1.x * ci[4]; d[5] = rb1.y * ci[5];
        d[6] = rb1.z * ci[6]; d[7] = rb1.w * ci[7];
    };

    auto compute = [&](int buf) {
        #pragma unroll
        for (int ks = 0; ks < 2; ks++) {
            const int kb = ks * 8 + (lane & 3);
            const int rbase = wmi * 32 + (lane >> 2);
            uint32_t ahi[2][4], alo[2][4];
            #pragma unroll
            for (int mf = 0; mf < 2; mf++) {
                float r[4];
                r[0] = As[buf][kb  ][rbase + mf*16];
                r[1] = As[buf][kb  ][rbase + mf*16 + 8];
                r[2] = As[buf][kb+4][rbase + mf*16];
                r[3] = As[buf][kb+4][rbase + mf*16 + 8];
                #pragma unroll
                for (int q = 0; q < 4; q++) {
                    float h = tf32r(r[q]);
                    ahi[mf][q] = __float_as_uint(h);
                    alo[mf][q] = __float_as_uint(tf32r(r[q] - h));
                }
            }
            #pragma unroll
            for (int nf = 0; nf < 8; nf++) {
                const int nidx = wni * 64 + nf * 8 + (lane >> 2);
                float b0r = Bs[buf][kb  ][nidx];
                float b1r = Bs[buf][kb+4][nidx];
                float bh0f = tf32r(b0r), bh1f = tf32r(b1r);
                uint32_t bh0 = __float_as_uint(bh0f);
                uint32_t bh1 = __float_as_uint(bh1f);
                uint32_t bl0 = __float_as_uint(tf32r(b0r - bh0f));
                uint32_t bl1 = __float_as_uint(tf32r(b1r - bh1f));
                mma_tf32(acc[0][nf], ahi[0], bh0, bh1);
                mma_tf32(acc[1][nf], ahi[1], bh0, bh1);
                mma_tf32(acc[0][nf], ahi[0], bl0, bl1);
                mma_tf32(acc[1][nf], ahi[1], bl0, bl1);
                mma_tf32(acc[0][nf], alo[0], bh0, bh1);
                mma_tf32(acc[1][nf], alo[1], bh0, bh1);
            }
        }
    };

    loadg(0);
    stage(0);
    __syncthreads();

    for (int k0 = 0, it = 0; k0 < DD; k0 += 16, it++) {
        const int buf = it & 1;
        const bool more = (k0 + 16) < DD;
        if (more) loadg(k0 + 16);
        compute(buf);
        if (more) stage(buf ^ 1);
        __syncthreads();
    }

    #pragma unroll
    for (int mf = 0; mf < 2; mf++) {
        const int r0 = i0 + wmi * 32 + mf * 16 + (lane >> 2);
        #pragma unroll
        for (int nf = 0; nf < 8; nf++) {
            const int c = j0 + wni * 64 + nf * 8 + (lane & 3) * 2;
            float2 w0 = {acc[mf][nf][0], acc[mf][nf][1]};
            float2 w1 = {acc[mf][nf][2], acc[mf][nf][3]};
            *(float2*)(g_logits + (size_t)r0 * SS + c) = w0;
            *(float2*)(g_logits + (size_t)(r0 + 8) * SS + c) = w1;
        }
    }
}

// ---------------- tf32 tensor-core GEMM (modes 1..4) ----------------
// MODE1: xs = disp^T @ (xn*W)  (A k-major; W fused into B stage), scatter-out
// MODE2: h  = gelu(xs @ w1 + b1)
// MODE3: ys = h @ w2 + b2
// MODE4: y  = comb @ ys_gathered
template<int MODE>
__global__ void __launch_bounds__(256, 2) gemm_tc(const float* __restrict__ Bext,
                                                   const float* __restrict__ biasext,
                                                   float* __restrict__ Cext,
                                                   const int* __restrict__ ca) {
    constexpr int KD = (MODE==1)?1024 : (MODE==2)?768 : (MODE==3)?2048 : 1024;
    constexpr int BK = 16;
    constexpr bool AKMAJ = (MODE==1);
    const int z = blockIdx.z;
    const int i0 = blockIdx.y * 128, j0 = blockIdx.x * 128;
    const int tid = threadIdx.x, lane = tid & 31, warp = tid >> 5;
    const int wmi = warp & 3;
    const int wni = warp >> 2;

    __shared__ float As[2][BK][136];
    __shared__ float Bs[2][BK][136];

    const float* Aptr = nullptr; int lda = 0;
    const float* Bptr = nullptr; int ldb = 0;
    if constexpr (MODE==1) { Aptr = g_disp + (size_t)z*1024*1024;
                             Bptr = g_xn  + (size_t)z*1024*768; ldb = 768; }
    if constexpr (MODE==2) { Aptr = g_xs + (size_t)z*256*768;   lda = 768;
                             Bptr = Bext + (size_t)z*768*2048;  ldb = 2048; }
    if constexpr (MODE==3) { Aptr = g_h  + (size_t)z*256*2048;  lda = 2048;
                             Bptr = Bext + (size_t)z*2048*768;  ldb = 768; }
    if constexpr (MODE==4) { Aptr = g_logits + (size_t)z*1024*1024; lda = 1024;
                             Bptr = g_ys; ldb = 768; }

    const int akk = tid >> 4, ac = (tid & 15) * 8;
    const int ar  = tid >> 1, akq = (tid & 1) * 8;

    float acc[2][8][4];
    #pragma unroll
    for (int mf = 0; mf < 2; mf++)
        #pragma unroll
        for (int nf = 0; nf < 8; nf++)
            #pragma unroll
            for (int q = 0; q < 4; q++) acc[mf][nf][q] = 0.f;

    float4 ra0, ra1, rb0, rb1, rw0, rw1;

    auto loadg = [&](int k0) {
        if constexpr (AKMAJ) {
            const float* p = Aptr + (size_t)(k0 + akk) * 1024 + i0 + ac;
            ra0 = *(const float4*)p; ra1 = *(const float4*)(p + 4);
        } else {
            const float* p = Aptr + (size_t)(i0 + ar) * lda + k0 + akq;
            ra0 = *(const float4*)p; ra1 = *(const float4*)(p + 4);
        }
        if constexpr (MODE==4) {
            int s = k0 + akk;
            const float* p = Bptr + (size_t)((s >> 5) * 256 + z * 32 + (s & 31)) * 768 + j0 + ac;
            rb0 = *(const float4*)p; rb1 = *(const float4*)(p + 4);
        } else {
            const float* p = Bptr + (size_t)(k0 + akk) * ldb + j0 + ac;
            rb0 = *(const float4*)p; rb1 = *(const float4*)(p + 4);
        }
        if constexpr (MODE==1) {
            int tok = z * 1024 + k0 + akk;
            int c = ca[(size_t)tok * KK];
            const float* w = g_W + (size_t)c * DD + j0 + ac;
            rw0 = *(const float4*)w; rw1 = *(const float4*)(w + 4);
        }
    };

    auto stage = [&](int buf) {
        if constexpr (AKMAJ) {
            float* d = &As[buf][akk][ac];
            d[0]=tf32r(ra0.x); d[1]=tf32r(ra0.y); d[2]=tf32r(ra0.z); d[3]=tf32r(ra0.w);
            d[4]=tf32r(ra1.x); d[5]=tf32r(ra1.y); d[6]=tf32r(ra1.z); d[7]=tf32r(ra1.w);
        } else {
            As[buf][akq+0][ar]=tf32r(ra0.x); As[buf][akq+1][ar]=tf32r(ra0.y);
            As[buf][akq+2][ar]=tf32r(ra0.z); As[buf][akq+3][ar]=tf32r(ra0.w);
            As[buf][akq+4][ar]=tf32r(ra1.x); As[buf][akq+5][ar]=tf32r(ra1.y);
            As[buf][akq+6][ar]=tf32r(ra1.z); As[buf][akq+7][ar]=tf32r(ra1.w);
        }
        float* d = &Bs[buf][akk][ac];
        if constexpr (MODE==1) {
            d[0]=tf32r(rb0.x*rw0.x); d[1]=tf32r(rb0.y*rw0.y);
            d[2]=tf32r(rb0.z*rw0.z); d[3]=tf32r(rb0.w*rw0.w);
            d[4]=tf32r(rb1.x*rw1.x); d[5]=tf32r(rb1.y*rw1.y);
            d[6]=tf32r(rb1.z*rw1.z); d[7]=tf32r(rb1.w*rw1.w);
        } else {
            d[0]=tf32r(rb0.x); d[1]=tf32r(rb0.y); d[2]=tf32r(rb0.z); d[3]=tf32r(rb0.w);
            d[4]=tf32r(rb1.x); d[5]=tf32r(rb1.y); d[6]=tf32r(rb1.z); d[7]=tf32r(rb1.w);
        }
    };

    auto compute = [&](int buf) {
        #pragma unroll
        for (int ks = 0; ks < 2; ks++) {
            const int kb = ks * 8 + (lane & 3);
            const int rbase = wmi * 32 + (lane >> 2);
            uint32_t af[2][4];
            #pragma unroll
            for (int mf = 0; mf < 2; mf++) {
                af[mf][0] = __float_as_uint(As[buf][kb  ][rbase + mf*16]);
                af[mf][1] = __float_as_uint(As[buf][kb  ][rbase + mf*16 + 8]);
                af[mf][2] = __float_as_uint(As[buf][kb+4][rbase + mf*16]);
                af[mf][3] = __float_as_uint(As[buf][kb+4][rbase + mf*16 + 8]);
            }
            #pragma unroll
            for (int nf = 0; nf < 8; nf++) {
                const int nidx = wni * 64 + nf * 8 + (lane >> 2);
                uint32_t bf0 = __float_as_uint(Bs[buf][kb  ][nidx]);
                uint32_t bf1 = __float_as_uint(Bs[buf][kb+4][nidx]);
                mma_tf32(acc[0][nf], af[0], bf0, bf1);
                mma_tf32(acc[1][nf], af[1], bf0, bf1);
            }
        }
    };

    loadg(0);
    stage(0);
    __syncthreads();

    for (int k0 = 0, it = 0; k0 < KD; k0 += BK, it++) {
        const int buf = it & 1;
        const bool more = (k0 + BK) < KD;
        if (more) loadg(k0 + BK);
        compute(buf);
        if (more) stage(buf ^ 1);
        __syncthreads();
    }

    #pragma unroll
    for (int mf = 0; mf < 2; mf++) {
        const int r0 = i0 + wmi * 32 + mf * 16 + (lane >> 2);
        #pragma unroll
        for (int nf = 0; nf < 8; nf++) {
            const int c = j0 + wni * 64 + nf * 8 + (lane & 3) * 2;
            float v00 = acc[mf][nf][0], v01 = acc[mf][nf][1];
            float v10 = acc[mf][nf][2], v11 = acc[mf][nf][3];
            if constexpr (MODE==2) {
                const float* bp = biasext + (size_t)z * 2048 + c;
                float bx = bp[0], by = bp[1];
                v00 = gelu_f(v00 + bx); v01 = gelu_f(v01 + by);
                v10 = gelu_f(v10 + bx); v11 = gelu_f(v11 + by);
            }
            if constexpr (MODE==3) {
                const float* bp = biasext + (size_t)z * 768 + c;
                float bx = bp[0], by = bp[1];
                v00 += bx; v01 += by; v10 += bx; v11 += by;
            }
            float* o0; float* o1;
            if constexpr (MODE==1) {
                int rr0 = r0, rr1 = r0 + 8;
                o0 = g_xs + (size_t)((rr0 >> 5) * 256 + z * 32 + (rr0 & 31)) * 768 + c;
                o1 = g_xs + (size_t)((rr1 >> 5) * 256 + z * 32 + (rr1 & 31)) * 768 + c;
            }
            if constexpr (MODE==2) {
                o0 = g_h + (size_t)z*256*2048 + (size_t)r0 * 2048 + c;
                o1 = o0 + (size_t)8 * 2048;
            }
            if constexpr (MODE==3) {
                o0 = g_ys + (size_t)z*256*768 + (size_t)r0 * 768 + c;
                o1 = o0 + (size_t)8 * 768;
            }
            if constexpr (MODE==4) {
                o0 = Cext + (size_t)z*1024*768 + (size_t)r0 * 768 + c;
                o1 = o0 + (size_t)8 * 768;
            }
            float2 w0 = {v00, v01}, w1 = {v10, v11};
            *(float2*)o0 = w0;
            *(float2*)o1 = w1;
        }
    }
}

// ---------------- top-k (K=8) per token + fused row softmax stats ----------------
__global__ void k_topk(float* __restrict__ mix, float* __restrict__ clus) {
    int warp = threadIdx.x >> 5, lane = threadIdx.x & 31;
    int row = blockIdx.x * 8 + warp;
    const float* L = g_logits + (size_t)row * SS;
    float v[32];
    #pragma unroll
    for (int j = 0; j < 32; j++) v[j] = L[j * 32 + lane];
    float lastv = INFINITY; int lasti = -1;
    float rmax = 0.f;
    #pragma unroll
    for (int sel = 0; sel < 8; sel++) {
        float bv = -INFINITY; int bi = 1 << 30;
        #pragma unroll
        for (int j = 0; j < 32; j++) {
            int gi = j * 32 + lane;
            float val = v[j];
            bool elig   = (val < lastv) || ((val == lastv) && (gi > lasti));
            bool better = (val > bv)    || ((val == bv)    && (gi < bi));
            if (elig && better) { bv = val; bi = gi; }
        }
        for (int o = 16; o; o >>= 1) {
            float ov = __shfl_xor_sync(0xffffffff, bv, o);
            int   oi = __shfl_xor_sync(0xffffffff, bi, o);
            if ((ov > bv) || ((ov == bv) && (oi < bi))) { bv = ov; bi = oi; }
        }
        lastv = bv; lasti = bi;
        if (sel == 0) rmax = bv;
        if (lane == 0 && mix) {
            mix [(size_t)row * 8 + sel] = bv;
            clus[(size_t)row * 8 + sel] = (float)(bi >> 5);
        }
    }
    // fused row softmax stats (comb denominator)
    float sm = 0.f;
    #pragma unroll
    for (int j = 0; j < 32; j++) sm += expf(v[j] - rmax);
    for (int o = 16; o; o >>= 1) sm += __shfl_xor_sync(0xffffffff, sm, o);
    if (lane == 0) { g_rowmax[row] = rmax; g_rowsum[row] = sm; }
}

// ---------------- disp softmax stats (over tokens) ----------------
__global__ void k_colstats() {
    int b = blockIdx.y, s0 = blockIdx.x * 32;
    int sl = threadIdx.x & 31, mr = threadIdx.x >> 5;
    const float* base = g_logits + (size_t)b * MM * SS + s0 + sl;
    float mx = -INFINITY;
    for (int m = mr; m < MM; m += 8) mx = fmaxf(mx, base[(size_t)m * SS]);
    __shared__ float pm[8][33], ps[8][33];
    pm[mr][sl] = mx; __syncthreads();
    if (mr == 0) { float v = pm[0][sl]; for (int r = 1; r < 8; r++) v = fmaxf(v, pm[r][sl]); pm[0][sl] = v; }
    __syncthreads();
    float cm = pm[0][sl];
    float sm = 0.f;
    for (int m = mr; m < MM; m += 8) sm += expf(base[(size_t)m * SS] - cm);
    ps[mr][sl] = sm; __syncthreads();
    if (mr == 0) {
        float v = 0.f; for (int r = 0; r < 8; r++) v += ps[r][sl];
        g_colmax[b * SS + s0 + sl] = cm;
        g_colsum[b * SS + s0 + sl] = v;
    }
}

__global__ void k_dispcomb() {
    int t = blockIdx.x, tid = threadIdx.x;
    int b = t >> 10;
    int j = tid * 4;
    float4 l  = *(float4*)(g_logits + (size_t)t * SS + j);
    float4 cm = *(float4*)(g_colmax + (size_t)b * SS + j);
    float4 cs = *(float4*)(g_colsum + (size_t)b * SS + j);
    float rm = g_rowmax[t], rs = g_rowsum[t];
    float4 dsp = { expf(l.x - cm.x)/cs.x, expf(l.y - cm.y)/cs.y,
                   expf(l.z - cm.z)/cs.z, expf(l.w - cm.w)/cs.w };
    float4 cb  = { expf(l.x - rm)/rs, expf(l.y - rm)/rs,
                   expf(l.z - rm)/rs, expf(l.w - rm)/rs };
    *(float4*)(g_disp   + (size_t)t * SS + j) = dsp;
    *(float4*)(g_logits + (size_t)t * SS + j) = cb;
}

// ---------------- launch ----------------
extern "C" void kernel_launch(void* const* d_in, const int* in_sizes, int n_in,
                              void* d_out, int out_size) {
    const float* x     = (const float*)d_in[0];
    const int*   ca    = (const int*)  d_in[1];
    const float* phi   = (const float*)d_in[2];
    const float* scale = (const float*)d_in[3];
    const float* w1    = (const float*)d_in[4];
    const float* b1    = (const float*)d_in[5];
    const float* w2    = (const float*)d_in[6];
    const float* b2    = (const float*)d_in[7];
    float* out = (float*)d_out;

    const int Y_ELEMS = BB * MM * DD;
    float* mixo = nullptr; float* cluso = nullptr;
    if (out_size >= Y_ELEMS + 2 * TT * KK) {
        mixo  = out + Y_ELEMS;
        cluso = mixo + TT * KK;
    }

    k_colinv<<<4, 256>>>(phi, scale);                 // 0
    k_norm_x<<<TT, 256>>>(x);                         // 1
    k_seg0<<<dim3(32, 6), 128>>>(ca);                 // 2
    k_seg1f<<<dim3(32, 6), 128>>>(ca);                // 3
    k_Wf<<<1, 1024>>>();                              // 4
    gemm_logits<<<dim3(8, 64), 256>>>(phi, ca);       // 5  <-- profiled by ncu -s 5 -c 1

    k_topk<<<1024, 256>>>(mixo, cluso);               // 6 (also row softmax stats)
    k_colstats<<<dim3(32, BB), 256>>>();              // 7
    k_dispcomb<<<TT, 256>>>();                        // 8

    gemm_tc<1><<<dim3(6, 8, BB), 256>>>(nullptr, nullptr, nullptr, ca); // xs
    gemm_tc<2><<<dim3(16, 2, NE), 256>>>(w1, b1, nullptr, ca);          // h
    gemm_tc<3><<<dim3(6, 2, NE), 256>>>(w2, b2, nullptr, ca);           // ys
    gemm_tc<4><<<dim3(6, 8, BB), 256>>>(nullptr, nullptr, out, ca);     // y
}

// round 5
// speedup vs baseline: 1.0729x; 1.0729x over previous
#include <cuda_runtime.h>
#include <math.h>
#include <stdint.h>

// ---------------- problem constants ----------------
#define BB   8
#define MM   1024
#define DD   768
#define NE   32
#define PE   32
#define KK   8
#define HH   2048
#define SS   1024            // N*P
#define TT   8192            // B*M
#define NG   256             // token groups for segment stats (32 tokens each)

// ---------------- scratch (device globals; no allocs allowed) ----------------
__device__ float g_xn   [TT * DD];          // unweighted normalized x
__device__ float g_colinv[SS];              // scale / ||phi_col||
__device__ float g_part [NG * NE * DD];     // seg0 partials (sum xn)       25 MB
__device__ float g_part2[NG * NE * DD];     // seg1 partials (sum |xn-mean|) 25 MB
__device__ int   g_icnt [NE];
__device__ float g_mean [NE * DD];
__device__ float g_mad  [NE * DD];
__device__ float g_W    [NE * DD];
__device__ float g_logits[TT * SS];         // logits, later overwritten by comb
__device__ float g_disp [TT * SS];
__device__ float g_rowmax[TT], g_rowsum[TT];
__device__ float g_colmax[BB * SS], g_colsum[BB * SS];
__device__ float g_xs [NE * (BB*PE) * DD];  // [n][b*32+p][d]
__device__ float g_h  [NE * (BB*PE) * HH];
__device__ float g_ys [NE * (BB*PE) * DD];

__device__ __forceinline__ float gelu_f(float v) {
    return 0.5f * v * (1.0f + erff(v * 0.70710678118654752440f));
}

__device__ __forceinline__ float tf32r(float x) {
    uint32_t r;
    asm("cvt.rna.tf32.f32 %0, %1;" : "=r"(r) : "f"(x));
    return __uint_as_float(r);
}

__device__ __forceinline__ void mma_tf32(float* c, const uint32_t* a,
                                         uint32_t b0, uint32_t b1) {
    asm volatile(
        "mma.sync.aligned.m16n8k8.row.col.f32.tf32.tf32.f32 "
        "{%0,%1,%2,%3}, {%4,%5,%6,%7}, {%8,%9}, {%0,%1,%2,%3};"
        : "+f"(c[0]), "+f"(c[1]), "+f"(c[2]), "+f"(c[3])
        : "r"(a[0]), "r"(a[1]), "r"(a[2]), "r"(a[3]), "r"(b0), "r"(b1));
}

// ---------------- phi column inverse norms (+ zero cluster counts) ----------------
__global__ void k_colinv(const float* __restrict__ phi, const float* __restrict__ scale) {
    int c = blockIdx.x * 256 + threadIdx.x;
    if (blockIdx.x == 0 && threadIdx.x < NE) g_icnt[threadIdx.x] = 0;
    float ss = 0.f;
    for (int d = 0; d < DD; d++) { float v = phi[(size_t)d * SS + c]; ss += v * v; }
    g_colinv[c] = scale[0] / fmaxf(sqrtf(ss), 1e-12f);
}

// ---------------- token L2 normalize ----------------
__global__ void k_norm_x(const float* __restrict__ x) {
    int t = blockIdx.x, tid = threadIdx.x;
    const float* xr = x + (size_t)t * DD;
    float v0 = xr[tid], v1 = xr[tid + 256], v2 = xr[tid + 512];
    __shared__ float red[256];
    red[tid] = v0*v0 + v1*v1 + v2*v2;
    __syncthreads();
    for (int o = 128; o; o >>= 1) { if (tid < o) red[tid] += red[tid+o]; __syncthreads(); }
    float inv = 1.0f / fmaxf(sqrtf(red[0]), 1e-12f);
    float* o = g_xn + (size_t)t * DD;
    o[tid] = v0*inv; o[tid+256] = v1*inv; o[tid+512] = v2*inv;
}

// ---------------- seg0: per-group per-cluster sums of xn ----------------
// grid (NG=256, 6), block 128; 32 tokens per group.
__global__ void k_seg0(const int* __restrict__ ca) {
    __shared__ float acc[NE][129];
    __shared__ int cs[32];
    int tid = threadIdx.x;
    int tg = blockIdx.x, d0 = blockIdx.y * 128;
    #pragma unroll
    for (int c = 0; c < NE; c++) acc[c][tid] = 0.f;
    if (tid < 32) {
        cs[tid] = ca[(size_t)(tg * 32 + tid) * KK];
        if (blockIdx.y == 0) atomicAdd(&g_icnt[cs[tid]], 1);   // integer: deterministic
    }
    __syncthreads();
    const float* base = g_xn + (size_t)(tg * 32) * DD + d0 + tid;
    #pragma unroll 4
    for (int tt = 0; tt < 32; tt++)
        acc[cs[tt]][tid] += base[(size_t)tt * DD];
    __syncthreads();
    #pragma unroll
    for (int c = 0; c < NE; c++)
        g_part[((size_t)tg * NE + c) * DD + d0 + tid] = acc[c][tid];
}

// ---------------- reduce seg0 partials -> mean ----------------
__global__ void k_red_mean() {
    int i = blockIdx.x * 256 + threadIdx.x;     // over 32*768
    if (i >= NE * DD) return;
    float s = 0.f;
    #pragma unroll 8
    for (int g = 0; g < NG; g++) s += g_part[(size_t)g * NE * DD + i];
    float cn = (float)g_icnt[i / DD];
    g_mean[i] = cn > 0.f ? s / cn : 0.f;
}

// ---------------- seg1: per-group per-cluster sums of |xn - mean| ----------------
__global__ void k_seg1(const int* __restrict__ ca) {
    __shared__ float acc[NE][129];
    __shared__ float meanS[NE][129];
    __shared__ int cs[32];
    int tid = threadIdx.x;
    int tg = blockIdx.x, d0 = blockIdx.y * 128;
    #pragma unroll
    for (int c = 0; c < NE; c++) {
        acc[c][tid] = 0.f;
        meanS[c][tid] = g_mean[c * DD + d0 + tid];
    }
    if (tid < 32) cs[tid] = ca[(size_t)(tg * 32 + tid) * KK];
    __syncthreads();
    const float* base = g_xn + (size_t)(tg * 32) * DD + d0 + tid;
    #pragma unroll 4
    for (int tt = 0; tt < 32; tt++) {
        int c = cs[tt];
        acc[c][tid] += fabsf(base[(size_t)tt * DD] - meanS[c][tid]);
    }
    __syncthreads();
    #pragma unroll
    for (int c = 0; c < NE; c++)
        g_part2[((size_t)tg * NE + c) * DD + d0 + tid] = acc[c][tid];
}

// ---------------- reduce seg1 partials -> mad ----------------
__global__ void k_red_mad() {
    int i = blockIdx.x * 256 + threadIdx.x;
    if (i >= NE * DD) return;
    float s = 0.f;
    #pragma unroll 8
    for (int g = 0; g < NG; g++) s += g_part2[(size_t)g * NE * DD + i];
    float cn = (float)g_icnt[i / DD];
    g_mad[i] = cn > 0.f ? s / cn : 0.f;
}

// ---------------- W clamp + renormalize (small) ----------------
__global__ void k_W() {
    __shared__ float red[1024];
    int tid = threadIdx.x;
    float l = 0.f;
    for (int i = tid; i < NE * DD; i += 1024) l += 1.0f / (g_mad[i] + 0.35f);
    red[tid] = l; __syncthreads();
    for (int o = 512; o; o >>= 1) { if (tid < o) red[tid] += red[tid+o]; __syncthreads(); }
    float top = 5.0f * red[0] / (float)(NE * DD);
    __syncthreads();
    float l2 = 0.f;
    for (int i = tid; i < NE * DD; i += 1024) l2 += fminf(1.0f / (g_mad[i] + 0.35f), top);
    red[tid] = l2; __syncthreads();
    for (int o = 512; o; o >>= 1) { if (tid < o) red[tid] += red[tid+o]; __syncthreads(); }
    float m2 = red[0] / (float)(NE * DD);
    __syncthreads();
    for (int i = tid; i < NE * DD; i += 1024)
        g_W[i] = fminf(1.0f / (g_mad[i] + 0.35f), top) / m2;
}

// ---------------- split-tf32 logits GEMM (exactness-preserving) ----------------
// logits[8192,1024] = (xn*W)[8192,768] @ (phi*colinv)[768,1024]
// 3-term split: hi*hi + hi*lo + lo*hi; abs error ~1e-8 -> top-k ordering safe.
__global__ void __launch_bounds__(256, 2) gemm_logits(const float* __restrict__ phi,
                                                      const int* __restrict__ ca) {
    const int i0 = blockIdx.y * 128, j0 = blockIdx.x * 128;
    const int tid = threadIdx.x, lane = tid & 31, warp = tid >> 5;
    const int wmi = warp & 3, wni = warp >> 2;

    __shared__ float As[2][16][136];
    __shared__ float Bs[2][16][136];

    const int ar = tid >> 1, akq = (tid & 1) * 8;
    const int akk = tid >> 4, ac = (tid & 15) * 8;
    const int token = i0 + ar;
    const int cc = ca[(size_t)token * KK];
    const float* Wrow = g_W + (size_t)cc * DD;
    float ci[8];
    #pragma unroll
    for (int q = 0; q < 8; q++) ci[q] = g_colinv[j0 + ac + q];

    float acc[2][8][4];
    #pragma unroll
    for (int mf = 0; mf < 2; mf++)
        #pragma unroll
        for (int nf = 0; nf < 8; nf++)
            #pragma unroll
            for (int q = 0; q < 4; q++) acc[mf][nf][q] = 0.f;

    float4 ra0, ra1, rw0, rw1, rb0, rb1;

    auto loadg = [&](int k0) {
        const float* p = g_xn + (size_t)token * DD + k0 + akq;
        ra0 = *(const float4*)p; ra1 = *(const float4*)(p + 4);
        const float* w = Wrow + k0 + akq;
        rw0 = *(const float4*)w; rw1 = *(const float4*)(w + 4);
        const float* pb = phi + (size_t)(k0 + akk) * SS + j0 + ac;
        rb0 = *(const float4*)pb; rb1 = *(const float4*)(pb + 4);
    };

    auto stage = [&](int buf) {
        As[buf][akq+0][ar] = ra0.x * rw0.x;
        As[buf][akq+1][ar] = ra0.y * rw0.y;
        As[buf][akq+2][ar] = ra0.z * rw0.z;
        As[buf][akq+3][ar] = ra0.w * rw0.w;
        As[buf][akq+4][ar] = ra1.x * rw1.x;
        As[buf][akq+5][ar] = ra1.y * rw1.y;
        As[buf][akq+6][ar] = ra1.z * rw1.z;
        As[buf][akq+7][ar] = ra1.w * rw1.w;
        float* d = &Bs[buf][akk][ac];
        d[0] = rb0.x * ci[0]; d[1] = rb0.y * ci[1];
        d[2] = rb0.z * ci[2]; d[3] = rb0.w * ci[3];
        d[4] = rb1.x * ci[4]; d[5] = rb1.y * ci[5];
        d[6] = rb1.z * ci[6]; d[7] = rb1.w * ci[7];
    };

    auto compute = [&](int buf) {
        #pragma unroll
        for (int ks = 0; ks < 2; ks++) {
            const int kb = ks * 8 + (lane & 3);
            const int rbase = wmi * 32 + (lane >> 2);
            uint32_t ahi[2][4], alo[2][4];
            #pragma unroll
            for (int mf = 0; mf < 2; mf++) {
                float r[4];
                r[0] = As[buf][kb  ][rbase + mf*16];
                r[1] = As[buf][kb  ][rbase + mf*16 + 8];
                r[2] = As[buf][kb+4][rbase + mf*16];
                r[3] = As[buf][kb+4][rbase + mf*16 + 8];
                #pragma unroll
                for (int q = 0; q < 4; q++) {
                    float h = tf32r(r[q]);
                    ahi[mf][q] = __float_as_uint(h);
                    alo[mf][q] = __float_as_uint(tf32r(r[q] - h));
                }
            }
            #pragma unroll
            for (int nf = 0; nf < 8; nf++) {
                const int nidx = wni * 64 + nf * 8 + (lane >> 2);
                float b0r = Bs[buf][kb  ][nidx];
                float b1r = Bs[buf][kb+4][nidx];
                float bh0f = tf32r(b0r), bh1f = tf32r(b1r);
                uint32_t bh0 = __float_as_uint(bh0f);
                uint32_t bh1 = __float_as_uint(bh1f);
                uint32_t bl0 = __float_as_uint(tf32r(b0r - bh0f));
                uint32_t bl1 = __float_as_uint(tf32r(b1r - bh1f));
                mma_tf32(acc[0][nf], ahi[0], bh0, bh1);
                mma_tf32(acc[1][nf], ahi[1], bh0, bh1);
                mma_tf32(acc[0][nf], ahi[0], bl0, bl1);
                mma_tf32(acc[1][nf], ahi[1], bl0, bl1);
                mma_tf32(acc[0][nf], alo[0], bh0, bh1);
                mma_tf32(acc[1][nf], alo[1], bh0, bh1);
            }
        }
    };

    loadg(0);
    stage(0);
    __syncthreads();

    for (int k0 = 0, it = 0; k0 < DD; k0 += 16, it++) {
        const int buf = it & 1;
        const bool more = (k0 + 16) < DD;
        if (more) loadg(k0 + 16);
        compute(buf);
        if (more) stage(buf ^ 1);
        __syncthreads();
    }

    #pragma unroll
    for (int mf = 0; mf < 2; mf++) {
        const int r0 = i0 + wmi * 32 + mf * 16 + (lane >> 2);
        #pragma unroll
        for (int nf = 0; nf < 8; nf++) {
            const int c = j0 + wni * 64 + nf * 8 + (lane & 3) * 2;
            float2 w0 = {acc[mf][nf][0], acc[mf][nf][1]};
            float2 w1 = {acc[mf][nf][2], acc[mf][nf][3]};
            *(float2*)(g_logits + (size_t)r0 * SS + c) = w0;
            *(float2*)(g_logits + (size_t)(r0 + 8) * SS + c) = w1;
        }
    }
}

// ---------------- tf32 tensor-core GEMM (modes 1..4) ----------------
// MODE1: xs = disp^T @ (xn*W)  (A k-major; W fused into B stage), scatter-out
// MODE2: h  = gelu(xs @ w1 + b1)
// MODE3: ys = h @ w2 + b2
// MODE4: y  = comb @ ys_gathered
template<int MODE>
__global__ void __launch_bounds__(256, 2) gemm_tc(const float* __restrict__ Bext,
                                                   const float* __restrict__ biasext,
                                                   float* __restrict__ Cext,
                                                   const int* __restrict__ ca) {
    constexpr int KD = (MODE==1)?1024 : (MODE==2)?768 : (MODE==3)?2048 : 1024;
    constexpr int BK = 16;
    constexpr bool AKMAJ = (MODE==1);
    const int z = blockIdx.z;
    const int i0 = blockIdx.y * 128, j0 = blockIdx.x * 128;
    const int tid = threadIdx.x, lane = tid & 31, warp = tid >> 5;
    const int wmi = warp & 3;
    const int wni = warp >> 2;

    __shared__ float As[2][BK][136];
    __shared__ float Bs[2][BK][136];

    const float* Aptr = nullptr; int lda = 0;
    const float* Bptr = nullptr; int ldb = 0;
    if constexpr (MODE==1) { Aptr = g_disp + (size_t)z*1024*1024;
                             Bptr = g_xn  + (size_t)z*1024*768; ldb = 768; }
    if constexpr (MODE==2) { Aptr = g_xs + (size_t)z*256*768;   lda = 768;
                             Bptr = Bext + (size_t)z*768*2048;  ldb = 2048; }
    if constexpr (MODE==3) { Aptr = g_h  + (size_t)z*256*2048;  lda = 2048;
                             Bptr = Bext + (size_t)z*2048*768;  ldb = 768; }
    if constexpr (MODE==4) { Aptr = g_logits + (size_t)z*1024*1024; lda = 1024;
                             Bptr = g_ys; ldb = 768; }

    const int akk = tid >> 4, ac = (tid & 15) * 8;
    const int ar  = tid >> 1, akq = (tid & 1) * 8;

    float acc[2][8][4];
    #pragma unroll
    for (int mf = 0; mf < 2; mf++)
        #pragma unroll
        for (int nf = 0; nf < 8; nf++)
            #pragma unroll
            for (int q = 0; q < 4; q++) acc[mf][nf][q] = 0.f;

    float4 ra0, ra1, rb0, rb1, rw0, rw1;

    auto loadg = [&](int k0) {
        if constexpr (AKMAJ) {
            const float* p = Aptr + (size_t)(k0 + akk) * 1024 + i0 + ac;
            ra0 = *(const float4*)p; ra1 = *(const float4*)(p + 4);
        } else {
            const float* p = Aptr + (size_t)(i0 + ar) * lda + k0 + akq;
            ra0 = *(const float4*)p; ra1 = *(const float4*)(p + 4);
        }
        if constexpr (MODE==4) {
            int s = k0 + akk;
            const float* p = Bptr + (size_t)((s >> 5) * 256 + z * 32 + (s & 31)) * 768 + j0 + ac;
            rb0 = *(const float4*)p; rb1 = *(const float4*)(p + 4);
        } else {
            const float* p = Bptr + (size_t)(k0 + akk) * ldb + j0 + ac;
            rb0 = *(const float4*)p; rb1 = *(const float4*)(p + 4);
        }
        if constexpr (MODE==1) {
            int tok = z * 1024 + k0 + akk;
            int c = ca[(size_t)tok * KK];
            const float* w = g_W + (size_t)c * DD + j0 + ac;
            rw0 = *(const float4*)w; rw1 = *(const float4*)(w + 4);
        }
    };

    auto stage = [&](int buf) {
        if constexpr (AKMAJ) {
            float* d = &As[buf][akk][ac];
            d[0]=tf32r(ra0.x); d[1]=tf32r(ra0.y); d[2]=tf32r(ra0.z); d[3]=tf32r(ra0.w);
            d[4]=tf32r(ra1.x); d[5]=tf32r(ra1.y); d[6]=tf32r(ra1.z); d[7]=tf32r(ra1.w);
        } else {
            As[buf][akq+0][ar]=tf32r(ra0.x); As[buf][akq+1][ar]=tf32r(ra0.y);
            As[buf][akq+2][ar]=tf32r(ra0.z); As[buf][akq+3][ar]=tf32r(ra0.w);
            As[buf][akq+4][ar]=tf32r(ra1.x); As[buf][akq+5][ar]=tf32r(ra1.y);
            As[buf][akq+6][ar]=tf32r(ra1.z); As[buf][akq+7][ar]=tf32r(ra1.w);
        }
        float* d = &Bs[buf][akk][ac];
        if constexpr (MODE==1) {
            d[0]=tf32r(rb0.x*rw0.x); d[1]=tf32r(rb0.y*rw0.y);
            d[2]=tf32r(rb0.z*rw0.z); d[3]=tf32r(rb0.w*rw0.w);
            d[4]=tf32r(rb1.x*rw1.x); d[5]=tf32r(rb1.y*rw1.y);
            d[6]=tf32r(rb1.z*rw1.z); d[7]=tf32r(rb1.w*rw1.w);
        } else {
            d[0]=tf32r(rb0.x); d[1]=tf32r(rb0.y); d[2]=tf32r(rb0.z); d[3]=tf32r(rb0.w);
            d[4]=tf32r(rb1.x); d[5]=tf32r(rb1.y); d[6]=tf32r(rb1.z); d[7]=tf32r(rb1.w);
        }
    };

    auto compute = [&](int buf) {
        #pragma unroll
        for (int ks = 0; ks < 2; ks++) {
            const int kb = ks * 8 + (lane & 3);
            const int rbase = wmi * 32 + (lane >> 2);
            uint32_t af[2][4];
            #pragma unroll
            for (int mf = 0; mf < 2; mf++) {
                af[mf][0] = __float_as_uint(As[buf][kb  ][rbase + mf*16]);
                af[mf][1] = __float_as_uint(As[buf][kb  ][rbase + mf*16 + 8]);
                af[mf][2] = __float_as_uint(As[buf][kb+4][rbase + mf*16]);
                af[mf][3] = __float_as_uint(As[buf][kb+4][rbase + mf*16 + 8]);
            }
            #pragma unroll
            for (int nf = 0; nf < 8; nf++) {
                const int nidx = wni * 64 + nf * 8 + (lane >> 2);
                uint32_t bf0 = __float_as_uint(Bs[buf][kb  ][nidx]);
                uint32_t bf1 = __float_as_uint(Bs[buf][kb+4][nidx]);
                mma_tf32(acc[0][nf], af[0], bf0, bf1);
                mma_tf32(acc[1][nf], af[1], bf0, bf1);
            }
        }
    };

    loadg(0);
    stage(0);
    __syncthreads();

    for (int k0 = 0, it = 0; k0 < KD; k0 += BK, it++) {
        const int buf = it & 1;
        const bool more = (k0 + BK) < KD;
        if (more) loadg(k0 + BK);
        compute(buf);
        if (more) stage(buf ^ 1);
        __syncthreads();
    }

    #pragma unroll
    for (int mf = 0; mf < 2; mf++) {
        const int r0 = i0 + wmi * 32 + mf * 16 + (lane >> 2);
        #pragma unroll
        for (int nf = 0; nf < 8; nf++) {
            const int c = j0 + wni * 64 + nf * 8 + (lane & 3) * 2;
            float v00 = acc[mf][nf][0], v01 = acc[mf][nf][1];
            float v10 = acc[mf][nf][2], v11 = acc[mf][nf][3];
            if constexpr (MODE==2) {
                const float* bp = biasext + (size_t)z * 2048 + c;
                float bx = bp[0], by = bp[1];
                v00 = gelu_f(v00 + bx); v01 = gelu_f(v01 + by);
                v10 = gelu_f(v10 + bx); v11 = gelu_f(v11 + by);
            }
            if constexpr (MODE==3) {
                const float* bp = biasext + (size_t)z * 768 + c;
                float bx = bp[0], by = bp[1];
                v00 += bx; v01 += by; v10 += bx; v11 += by;
            }
            float* o0; float* o1;
            if constexpr (MODE==1) {
                int rr0 = r0, rr1 = r0 + 8;
                o0 = g_xs + (size_t)((rr0 >> 5) * 256 + z * 32 + (rr0 & 31)) * 768 + c;
                o1 = g_xs + (size_t)((rr1 >> 5) * 256 + z * 32 + (rr1 & 31)) * 768 + c;
            }
            if constexpr (MODE==2) {
                o0 = g_h + (size_t)z*256*2048 + (size_t)r0 * 2048 + c;
                o1 = o0 + (size_t)8 * 2048;
            }
            if constexpr (MODE==3) {
                o0 = g_ys + (size_t)z*256*768 + (size_t)r0 * 768 + c;
                o1 = o0 + (size_t)8 * 768;
            }
            if constexpr (MODE==4) {
                o0 = Cext + (size_t)z*1024*768 + (size_t)r0 * 768 + c;
                o1 = o0 + (size_t)8 * 768;
            }
            float2 w0 = {v00, v01}, w1 = {v10, v11};
            *(float2*)o0 = w0;
            *(float2*)o1 = w1;
        }
    }
}

// ---------------- top-k (K=8) per token + fused row softmax stats ----------------
__global__ void k_topk(float* __restrict__ mix, float* __restrict__ clus) {
    int warp = threadIdx.x >> 5, lane = threadIdx.x & 31;
    int row = blockIdx.x * 8 + warp;
    const float* L = g_logits + (size_t)row * SS;
    float v[32];
    #pragma unroll
    for (int j = 0; j < 32; j++) v[j] = L[j * 32 + lane];
    float lastv = INFINITY; int lasti = -1;
    float rmax = 0.f;
    #pragma unroll
    for (int sel = 0; sel < 8; sel++) {
        float bv = -INFINITY; int bi = 1 << 30;
        #pragma unroll
        for (int j = 0; j < 32; j++) {
            int gi = j * 32 + lane;
            float val = v[j];
            bool elig   = (val < lastv) || ((val == lastv) && (gi > lasti));
            bool better = (val > bv)    || ((val == bv)    && (gi < bi));
            if (elig && better) { bv = val; bi = gi; }
        }
        for (int o = 16; o; o >>= 1) {
            float ov = __shfl_xor_sync(0xffffffff, bv, o);
            int   oi = __shfl_xor_sync(0xffffffff, bi, o);
            if ((ov > bv) || ((ov == bv) && (oi < bi))) { bv = ov; bi = oi; }
        }
        lastv = bv; lasti = bi;
        if (sel == 0) rmax = bv;
        if (lane == 0 && mix) {
            mix [(size_t)row * 8 + sel] = bv;
            clus[(size_t)row * 8 + sel] = (float)(bi >> 5);
        }
    }
    float sm = 0.f;
    #pragma unroll
    for (int j = 0; j < 32; j++) sm += expf(v[j] - rmax);
    for (int o = 16; o; o >>= 1) sm += __shfl_xor_sync(0xffffffff, sm, o);
    if (lane == 0) { g_rowmax[row] = rmax; g_rowsum[row] = sm; }
}

// ---------------- disp softmax stats (over tokens) ----------------
__global__ void k_colstats() {
    int b = blockIdx.y, s0 = blockIdx.x * 32;
    int sl = threadIdx.x & 31, mr = threadIdx.x >> 5;
    const float* base = g_logits + (size_t)b * MM * SS + s0 + sl;
    float mx = -INFINITY;
    for (int m = mr; m < MM; m += 8) mx = fmaxf(mx, base[(size_t)m * SS]);
    __shared__ float pm[8][33], ps[8][33];
    pm[mr][sl] = mx; __syncthreads();
    if (mr == 0) { float v = pm[0][sl]; for (int r = 1; r < 8; r++) v = fmaxf(v, pm[r][sl]); pm[0][sl] = v; }
    __syncthreads();
    float cm = pm[0][sl];
    float sm = 0.f;
    for (int m = mr; m < MM; m += 8) sm += expf(base[(size_t)m * SS] - cm);
    ps[mr][sl] = sm; __syncthreads();
    if (mr == 0) {
        float v = 0.f; for (int r = 0; r < 8; r++) v += ps[r][sl];
        g_colmax[b * SS + s0 + sl] = cm;
        g_colsum[b * SS + s0 + sl] = v;
    }
}

__global__ void k_dispcomb() {
    int t = blockIdx.x, tid = threadIdx.x;
    int b = t >> 10;
    int j = tid * 4;
    float4 l  = *(float4*)(g_logits + (size_t)t * SS + j);
    float4 cm = *(float4*)(g_colmax + (size_t)b * SS + j);
    float4 cs = *(float4*)(g_colsum + (size_t)b * SS + j);
    float rm = g_rowmax[t], rs = g_rowsum[t];
    float4 dsp = { expf(l.x - cm.x)/cs.x, expf(l.y - cm.y)/cs.y,
                   expf(l.z - cm.z)/cs.z, expf(l.w - cm.w)/cs.w };
    float4 cb  = { expf(l.x - rm)/rs, expf(l.y - rm)/rs,
                   expf(l.z - rm)/rs, expf(l.w - rm)/rs };
    *(float4*)(g_disp   + (size_t)t * SS + j) = dsp;
    *(float4*)(g_logits + (size_t)t * SS + j) = cb;
}

// ---------------- launch ----------------
extern "C" void kernel_launch(void* const* d_in, const int* in_sizes, int n_in,
                              void* d_out, int out_size) {
    const float* x     = (const float*)d_in[0];
    const int*   ca    = (const int*)  d_in[1];
    const float* phi   = (const float*)d_in[2];
    const float* scale = (const float*)d_in[3];
    const float* w1    = (const float*)d_in[4];
    const float* b1    = (const float*)d_in[5];
    const float* w2    = (const float*)d_in[6];
    const float* b2    = (const float*)d_in[7];
    float* out = (float*)d_out;

    const int Y_ELEMS = BB * MM * DD;
    float* mixo = nullptr; float* cluso = nullptr;
    if (out_size >= Y_ELEMS + 2 * TT * KK) {
        mixo  = out + Y_ELEMS;
        cluso = mixo + TT * KK;
    }

    k_colinv<<<4, 256>>>(phi, scale);                 // 0 (also zeroes counts)
    k_norm_x<<<TT, 256>>>(x);                         // 1
    k_seg0<<<dim3(NG, 6), 128>>>(ca);                 // 2
    k_red_mean<<<96, 256>>>();                        // 3
    k_seg1<<<dim3(NG, 6), 128>>>(ca);                 // 4
    k_red_mad<<<96, 256>>>();                         // 5  <-- ncu -s 5 -c 1 lands here
    k_W<<<1, 1024>>>();                               // 6
    gemm_logits<<<dim3(8, 64), 256>>>(phi, ca);       // 7

    k_topk<<<1024, 256>>>(mixo, cluso);               // 8 (also row softmax stats)
    k_colstats<<<dim3(32, BB), 256>>>();              // 9
    k_dispcomb<<<TT, 256>>>();                        // 10

    gemm_tc<1><<<dim3(6, 8, BB), 256>>>(nullptr, nullptr, nullptr, ca); // xs
    gemm_tc<2><<<dim3(16, 2, NE), 256>>>(w1, b1, nullptr, ca);          // h
    gemm_tc<3><<<dim3(6, 2, NE), 256>>>(w2, b2, nullptr, ca);           // ys
    gemm_tc<4><<<dim3(6, 8, BB), 256>>>(nullptr, nullptr, out, ca);     // y
}

// round 6
// speedup vs baseline: 1.2145x; 1.1320x over previous
#include <cuda_runtime.h>
#include <math.h>
#include <stdint.h>

// ---------------- problem constants ----------------
#define BB   8
#define MM   1024
#define DD   768
#define NE   32
#define PE   32
#define KK   8
#define HH   2048
#define SS   1024            // N*P
#define TT   8192            // B*M
#define NG   256             // token groups for segment stats (32 tokens each)
#define STAGES 3

// ---------------- scratch (device globals; no allocs allowed) ----------------
__device__ float g_xn   [TT * DD];          // unweighted normalized x
__device__ float g_xnw  [TT * DD];          // xn * W[ca]  (ACMoE-weighted)
__device__ float g_phin [DD * SS];          // phi * scale / ||col||
__device__ float g_part [NG * NE * DD];
__device__ float g_part2[NG * NE * DD];
__device__ int   g_icnt [NE];
__device__ float g_mean [NE * DD];
__device__ float g_mad  [NE * DD];
__device__ float g_W    [NE * DD];
__device__ float g_logits[TT * SS];         // logits, later overwritten by comb
__device__ float g_disp [TT * SS];
__device__ float g_rowmax[TT], g_rowsum[TT];
__device__ float g_colmax[BB * SS], g_colsum[BB * SS];
__device__ float g_xs [NE * (BB*PE) * DD];
__device__ float g_h  [NE * (BB*PE) * HH];
__device__ float g_ys [NE * (BB*PE) * DD];

__device__ __forceinline__ float gelu_f(float v) {
    return 0.5f * v * (1.0f + erff(v * 0.70710678118654752440f));
}

__device__ __forceinline__ float tf32r(float x) {
    uint32_t r;
    asm("cvt.rna.tf32.f32 %0, %1;" : "=r"(r) : "f"(x));
    return __uint_as_float(r);
}

__device__ __forceinline__ void mma_tf32(float* c, const uint32_t* a,
                                         uint32_t b0, uint32_t b1) {
    asm volatile(
        "mma.sync.aligned.m16n8k8.row.col.f32.tf32.tf32.f32 "
        "{%0,%1,%2,%3}, {%4,%5,%6,%7}, {%8,%9}, {%0,%1,%2,%3};"
        : "+f"(c[0]), "+f"(c[1]), "+f"(c[2]), "+f"(c[3])
        : "r"(a[0]), "r"(a[1]), "r"(a[2]), "r"(a[3]), "r"(b0), "r"(b1));
}

__device__ __forceinline__ void cpasync16(uint32_t dst, const void* src) {
    asm volatile("cp.async.ca.shared.global [%0], [%1], 16;" :: "r"(dst), "l"(src));
}
#define CP_COMMIT()  asm volatile("cp.async.commit_group;" ::: "memory")
#define CP_WAIT1()   asm volatile("cp.async.wait_group 1;"  ::: "memory")

// ---------------- phin = phi * scale/||col||  (+ zero cluster counts) ----------------
__global__ void k_phin(const float* __restrict__ phi, const float* __restrict__ scale) {
    int c = blockIdx.x * 256 + threadIdx.x;
    if (blockIdx.x == 0 && threadIdx.x < NE) g_icnt[threadIdx.x] = 0;
    float ss = 0.f;
    for (int d = 0; d < DD; d++) { float v = phi[(size_t)d * SS + c]; ss += v * v; }
    float inv = scale[0] / fmaxf(sqrtf(ss), 1e-12f);
    for (int d = 0; d < DD; d++) g_phin[(size_t)d * SS + c] = phi[(size_t)d * SS + c] * inv;
}

// ---------------- token L2 normalize ----------------
__global__ void k_norm_x(const float* __restrict__ x) {
    int t = blockIdx.x, tid = threadIdx.x;
    const float* xr = x + (size_t)t * DD;
    float v0 = xr[tid], v1 = xr[tid + 256], v2 = xr[tid + 512];
    __shared__ float red[256];
    red[tid] = v0*v0 + v1*v1 + v2*v2;
    __syncthreads();
    for (int o = 128; o; o >>= 1) { if (tid < o) red[tid] += red[tid+o]; __syncthreads(); }
    float inv = 1.0f / fmaxf(sqrtf(red[0]), 1e-12f);
    float* o = g_xn + (size_t)t * DD;
    o[tid] = v0*inv; o[tid+256] = v1*inv; o[tid+512] = v2*inv;
}

// ---------------- seg0: per-group per-cluster sums of xn ----------------
__global__ void k_seg0(const int* __restrict__ ca) {
    __shared__ float acc[NE][129];
    __shared__ int cs[32];
    int tid = threadIdx.x;
    int tg = blockIdx.x, d0 = blockIdx.y * 128;
    #pragma unroll
    for (int c = 0; c < NE; c++) acc[c][tid] = 0.f;
    if (tid < 32) {
        cs[tid] = ca[(size_t)(tg * 32 + tid) * KK];
        if (blockIdx.y == 0) atomicAdd(&g_icnt[cs[tid]], 1);
    }
    __syncthreads();
    const float* base = g_xn + (size_t)(tg * 32) * DD + d0 + tid;
    #pragma unroll 4
    for (int tt = 0; tt < 32; tt++)
        acc[cs[tt]][tid] += base[(size_t)tt * DD];
    __syncthreads();
    #pragma unroll
    for (int c = 0; c < NE; c++)
        g_part[((size_t)tg * NE + c) * DD + d0 + tid] = acc[c][tid];
}

__global__ void k_red_mean() {
    int i = blockIdx.x * 256 + threadIdx.x;
    if (i >= NE * DD) return;
    float s = 0.f;
    #pragma unroll 8
    for (int g = 0; g < NG; g++) s += g_part[(size_t)g * NE * DD + i];
    float cn = (float)g_icnt[i / DD];
    g_mean[i] = cn > 0.f ? s / cn : 0.f;
}

__global__ void k_seg1(const int* __restrict__ ca) {
    __shared__ float acc[NE][129];
    __shared__ float meanS[NE][129];
    __shared__ int cs[32];
    int tid = threadIdx.x;
    int tg = blockIdx.x, d0 = blockIdx.y * 128;
    #pragma unroll
    for (int c = 0; c < NE; c++) {
        acc[c][tid] = 0.f;
        meanS[c][tid] = g_mean[c * DD + d0 + tid];
    }
    if (tid < 32) cs[tid] = ca[(size_t)(tg * 32 + tid) * KK];
    __syncthreads();
    const float* base = g_xn + (size_t)(tg * 32) * DD + d0 + tid;
    #pragma unroll 4
    for (int tt = 0; tt < 32; tt++) {
        int c = cs[tt];
        acc[c][tid] += fabsf(base[(size_t)tt * DD] - meanS[c][tid]);
    }
    __syncthreads();
    #pragma unroll
    for (int c = 0; c < NE; c++)
        g_part2[((size_t)tg * NE + c) * DD + d0 + tid] = acc[c][tid];
}

__global__ void k_red_mad() {
    int i = blockIdx.x * 256 + threadIdx.x;
    if (i >= NE * DD) return;
    float s = 0.f;
    #pragma unroll 8
    for (int g = 0; g < NG; g++) s += g_part2[(size_t)g * NE * DD + i];
    float cn = (float)g_icnt[i / DD];
    g_mad[i] = cn > 0.f ? s / cn : 0.f;
}

__global__ void k_W() {
    __shared__ float red[1024];
    int tid = threadIdx.x;
    float l = 0.f;
    for (int i = tid; i < NE * DD; i += 1024) l += 1.0f / (g_mad[i] + 0.35f);
    red[tid] = l; __syncthreads();
    for (int o = 512; o; o >>= 1) { if (tid < o) red[tid] += red[tid+o]; __syncthreads(); }
    float top = 5.0f * red[0] / (float)(NE * DD);
    __syncthreads();
    float l2 = 0.f;
    for (int i = tid; i < NE * DD; i += 1024) l2 += fminf(1.0f / (g_mad[i] + 0.35f), top);
    red[tid] = l2; __syncthreads();
    for (int o = 512; o; o >>= 1) { if (tid < o) red[tid] += red[tid+o]; __syncthreads(); }
    float m2 = red[0] / (float)(NE * DD);
    __syncthreads();
    for (int i = tid; i < NE * DD; i += 1024)
        g_W[i] = fminf(1.0f / (g_mad[i] + 0.35f), top) / m2;
}

// ---------------- xnw = xn * W[ca] ----------------
__global__ void k_apply(const int* __restrict__ ca) {
    int t = blockIdx.x, tid = threadIdx.x;
    int c = ca[(size_t)t * KK];
    const float* Wr = g_W + (size_t)c * DD;
    const float* xr = g_xn + (size_t)t * DD;
    float* o = g_xnw + (size_t)t * DD;
    o[tid]       = xr[tid]       * Wr[tid];
    o[tid + 256] = xr[tid + 256] * Wr[tid + 256];
    o[tid + 512] = xr[tid + 512] * Wr[tid + 512];
}

// ---------------- unified tf32 tensor-core GEMM, cp.async 3-stage ----------------
// MODE0: logits = xnw[8192,768] @ phin[768,1024]   (3-term tf32 split, order-exact)
// MODE1: xs = disp^T[1024,1024] @ xnw_b[1024,768]  (A k-major), scatter-out
// MODE2: h  = gelu(xs[256,768] @ w1[768,2048] + b1)
// MODE3: ys = h[256,2048] @ w2[2048,768] + b2
// MODE4: y  = comb[1024,1024] @ ys_gathered[1024,768]
template<int MODE>
__global__ void __launch_bounds__(256, 2) gemm_tc(const float* __restrict__ Bext,
                                                   const float* __restrict__ biasext,
                                                   float* __restrict__ Cext,
                                                   const int* __restrict__ ca) {
    constexpr int KD = (MODE==0)?768 : (MODE==1)?1024 : (MODE==2)?768 : (MODE==3)?2048 : 1024;
    constexpr int BK = 16;
    constexpr int NT = KD / BK;
    constexpr bool AKMAJ = (MODE==1);
    constexpr bool SPLIT = (MODE==0);
    constexpr int ASZ = AKMAJ ? 16*136 : 128*20;   // floats per stage
    constexpr int BSZ = 16*136;

    const int z = blockIdx.z;
    const int i0 = blockIdx.y * 128, j0 = blockIdx.x * 128;
    const int tid = threadIdx.x, lane = tid & 31, warp = tid >> 5;
    const int wmi = warp & 3, wni = warp >> 2;

    extern __shared__ float smem[];
    float* Asm = smem;
    float* Bsm = smem + STAGES * ASZ;
    const uint32_t As_u = (uint32_t)__cvta_generic_to_shared(Asm);
    const uint32_t Bs_u = (uint32_t)__cvta_generic_to_shared(Bsm);

    const float* Aptr = nullptr; int lda = 0;
    const float* Bptr = nullptr; int ldb = 0;
    if constexpr (MODE==0) { Aptr = g_xnw;  lda = 768;  Bptr = g_phin; ldb = 1024; }
    if constexpr (MODE==1) { Aptr = g_disp + (size_t)z*1024*1024;
                             Bptr = g_xnw + (size_t)z*1024*768; ldb = 768; }
    if constexpr (MODE==2) { Aptr = g_xs + (size_t)z*256*768;   lda = 768;
                             Bptr = Bext + (size_t)z*768*2048;  ldb = 2048; }
    if constexpr (MODE==3) { Aptr = g_h  + (size_t)z*256*2048;  lda = 2048;
                             Bptr = Bext + (size_t)z*2048*768;  ldb = 768; }
    if constexpr (MODE==4) { Aptr = g_logits + (size_t)z*1024*1024; lda = 1024;
                             Bptr = g_ys; ldb = 768; }

    float acc[2][8][4];
    #pragma unroll
    for (int mf = 0; mf < 2; mf++)
        #pragma unroll
        for (int nf = 0; nf < 8; nf++)
            #pragma unroll
            for (int q = 0; q < 4; q++) acc[mf][nf][q] = 0.f;

    auto issue = [&](int it) {
        const int k0 = it * BK;
        const int st = it % STAGES;
        #pragma unroll
        for (int q = 0; q < 2; q++) {
            int c = tid + q * 256;
            if constexpr (AKMAJ) {
                int kk = c >> 5, col = (c & 31) * 4;
                cpasync16(As_u + (uint32_t)(st*ASZ + kk*136 + col) * 4,
                          Aptr + (size_t)(k0 + kk) * 1024 + i0 + col);
            } else {
                int row = c >> 2, col = (c & 3) * 4;
                cpasync16(As_u + (uint32_t)(st*ASZ + row*20 + col) * 4,
                          Aptr + (size_t)(i0 + row) * lda + k0 + col);
            }
        }
        #pragma unroll
        for (int q = 0; q < 2; q++) {
            int c = tid + q * 256;
            int kk = c >> 5, col = (c & 31) * 4;
            const float* src;
            if constexpr (MODE==4) {
                int s = k0 + kk;
                src = Bptr + (size_t)((s >> 5) * 256 + z * 32 + (s & 31)) * 768 + j0 + col;
            } else {
                src = Bptr + (size_t)(k0 + kk) * ldb + j0 + col;
            }
            cpasync16(Bs_u + (uint32_t)(st*BSZ + kk*136 + col) * 4, src);
        }
    };

    auto compute = [&](int st) {
        const float* A = Asm + st * ASZ;
        const float* B = Bsm + st * BSZ;
        #pragma unroll
        for (int ks = 0; ks < 2; ks++) {
            const int kq = ks * 8 + (lane & 3);
            const int rbase = wmi * 32 + (lane >> 2);
            float ar[2][4];
            #pragma unroll
            for (int mf = 0; mf < 2; mf++) {
                if constexpr (AKMAJ) {
                    ar[mf][0] = A[kq*136     + rbase + mf*16];
                    ar[mf][1] = A[kq*136     + rbase + mf*16 + 8];
                    ar[mf][2] = A[(kq+4)*136 + rbase + mf*16];
                    ar[mf][3] = A[(kq+4)*136 + rbase + mf*16 + 8];
                } else {
                    ar[mf][0] = A[(rbase + mf*16    )*20 + kq];
                    ar[mf][1] = A[(rbase + mf*16 + 8)*20 + kq];
                    ar[mf][2] = A[(rbase + mf*16    )*20 + kq + 4];
                    ar[mf][3] = A[(rbase + mf*16 + 8)*20 + kq + 4];
                }
            }
            uint32_t ahi[2][4], alo[2][4];
            #pragma unroll
            for (int mf = 0; mf < 2; mf++)
                #pragma unroll
                for (int q = 0; q < 4; q++) {
                    float h = tf32r(ar[mf][q]);
                    ahi[mf][q] = __float_as_uint(h);
                    if constexpr (SPLIT) alo[mf][q] = __float_as_uint(tf32r(ar[mf][q] - h));
                }
            #pragma unroll
            for (int nf = 0; nf < 8; nf++) {
                const int nidx = wni * 64 + nf * 8 + (lane >> 2);
                float b0r = B[kq*136 + nidx];
                float b1r = B[(kq+4)*136 + nidx];
                float bh0f = tf32r(b0r), bh1f = tf32r(b1r);
                uint32_t bh0 = __float_as_uint(bh0f), bh1 = __float_as_uint(bh1f);
                mma_tf32(acc[0][nf], ahi[0], bh0, bh1);
                mma_tf32(acc[1][nf], ahi[1], bh0, bh1);
                if constexpr (SPLIT) {
                    uint32_t bl0 = __float_as_uint(tf32r(b0r - bh0f));
                    uint32_t bl1 = __float_as_uint(tf32r(b1r - bh1f));
                    mma_tf32(acc[0][nf], ahi[0], bl0, bl1);
                    mma_tf32(acc[1][nf], ahi[1], bl0, bl1);
                    mma_tf32(acc[0][nf], alo[0], bh0, bh1);
                    mma_tf32(acc[1][nf], alo[1], bh0, bh1);
                }
            }
        }
    };

    issue(0); CP_COMMIT();
    issue(1); CP_COMMIT();

    for (int it = 0; it < NT; it++) {
        CP_WAIT1();
        __syncthreads();
        compute(it % STAGES);
        if (it + 2 < NT) issue(it + 2);
        CP_COMMIT();
    }

    // epilogue
    #pragma unroll
    for (int mf = 0; mf < 2; mf++) {
        const int r0 = i0 + wmi * 32 + mf * 16 + (lane >> 2);
        #pragma unroll
        for (int nf = 0; nf < 8; nf++) {
            const int c = j0 + wni * 64 + nf * 8 + (lane & 3) * 2;
            float v00 = acc[mf][nf][0], v01 = acc[mf][nf][1];
            float v10 = acc[mf][nf][2], v11 = acc[mf][nf][3];
            if constexpr (MODE==2) {
                const float* bp = biasext + (size_t)z * 2048 + c;
                float bx = bp[0], by = bp[1];
                v00 = gelu_f(v00 + bx); v01 = gelu_f(v01 + by);
                v10 = gelu_f(v10 + bx); v11 = gelu_f(v11 + by);
            }
            if constexpr (MODE==3) {
                const float* bp = biasext + (size_t)z * 768 + c;
                float bx = bp[0], by = bp[1];
                v00 += bx; v01 += by; v10 += bx; v11 += by;
            }
            float* o0; float* o1;
            if constexpr (MODE==0) {
                o0 = g_logits + (size_t)r0 * SS + c;
                o1 = o0 + (size_t)8 * SS;
            }
            if constexpr (MODE==1) {
                int rr0 = r0, rr1 = r0 + 8;
                o0 = g_xs + (size_t)((rr0 >> 5) * 256 + z * 32 + (rr0 & 31)) * 768 + c;
                o1 = g_xs + (size_t)((rr1 >> 5) * 256 + z * 32 + (rr1 & 31)) * 768 + c;
            }
            if constexpr (MODE==2) {
                o0 = g_h + (size_t)z*256*2048 + (size_t)r0 * 2048 + c;
                o1 = o0 + (size_t)8 * 2048;
            }
            if constexpr (MODE==3) {
                o0 = g_ys + (size_t)z*256*768 + (size_t)r0 * 768 + c;
                o1 = o0 + (size_t)8 * 768;
            }
            if constexpr (MODE==4) {
                o0 = Cext + (size_t)z*1024*768 + (size_t)r0 * 768 + c;
                o1 = o0 + (size_t)8 * 768;
            }
            float2 w0 = {v00, v01}, w1 = {v10, v11};
            *(float2*)o0 = w0;
            *(float2*)o1 = w1;
        }
    }
}

// ---------------- top-k (K=8) per token + fused row softmax stats ----------------
__global__ void k_topk(float* __restrict__ mix, float* __restrict__ clus) {
    int warp = threadIdx.x >> 5, lane = threadIdx.x & 31;
    int row = blockIdx.x * 8 + warp;
    const float* L = g_logits + (size_t)row * SS;
    float v[32];
    #pragma unroll
    for (int j = 0; j < 32; j++) v[j] = L[j * 32 + lane];
    float lastv = INFINITY; int lasti = -1;
    float rmax = 0.f;
    #pragma unroll
    for (int sel = 0; sel < 8; sel++) {
        float bv = -INFINITY; int bi = 1 << 30;
        #pragma unroll
        for (int j = 0; j < 32; j++) {
            int gi = j * 32 + lane;
            float val = v[j];
            bool elig   = (val < lastv) || ((val == lastv) && (gi > lasti));
            bool better = (val > bv)    || ((val == bv)    && (gi < bi));
            if (elig && better) { bv = val; bi = gi; }
        }
        for (int o = 16; o; o >>= 1) {
            float ov = __shfl_xor_sync(0xffffffff, bv, o);
            int   oi = __shfl_xor_sync(0xffffffff, bi, o);
            if ((ov > bv) || ((ov == bv) && (oi < bi))) { bv = ov; bi = oi; }
        }
        lastv = bv; lasti = bi;
        if (sel == 0) rmax = bv;
        if (lane == 0 && mix) {
            mix [(size_t)row * 8 + sel] = bv;
            clus[(size_t)row * 8 + sel] = (float)(bi >> 5);
        }
    }
    float sm = 0.f;
    #pragma unroll
    for (int j = 0; j < 32; j++) sm += expf(v[j] - rmax);
    for (int o = 16; o; o >>= 1) sm += __shfl_xor_sync(0xffffffff, sm, o);
    if (lane == 0) { g_rowmax[row] = rmax; g_rowsum[row] = sm; }
}

// ---------------- disp softmax stats (over tokens) ----------------
__global__ void k_colstats() {
    int b = blockIdx.y, s0 = blockIdx.x * 32;
    int sl = threadIdx.x & 31, mr = threadIdx.x >> 5;
    const float* base = g_logits + (size_t)b * MM * SS + s0 + sl;
    float mx = -INFINITY;
    for (int m = mr; m < MM; m += 8) mx = fmaxf(mx, base[(size_t)m * SS]);
    __shared__ float pm[8][33], ps[8][33];
    pm[mr][sl] = mx; __syncthreads();
    if (mr == 0) { float v = pm[0][sl]; for (int r = 1; r < 8; r++) v = fmaxf(v, pm[r][sl]); pm[0][sl] = v; }
    __syncthreads();
    float cm = pm[0][sl];
    float sm = 0.f;
    for (int m = mr; m < MM; m += 8) sm += expf(base[(size_t)m * SS] - cm);
    ps[mr][sl] = sm; __syncthreads();
    if (mr == 0) {
        float v = 0.f; for (int r = 0; r < 8; r++) v += ps[r][sl];
        g_colmax[b * SS + s0 + sl] = cm;
        g_colsum[b * SS + s0 + sl] = v;
    }
}

__global__ void k_dispcomb() {
    int t = blockIdx.x, tid = threadIdx.x;
    int b = t >> 10;
    int j = tid * 4;
    float4 l  = *(float4*)(g_logits + (size_t)t * SS + j);
    float4 cm = *(float4*)(g_colmax + (size_t)b * SS + j);
    float4 cs = *(float4*)(g_colsum + (size_t)b * SS + j);
    float rm = g_rowmax[t], rs = g_rowsum[t];
    float4 dsp = { expf(l.x - cm.x)/cs.x, expf(l.y - cm.y)/cs.y,
                   expf(l.z - cm.z)/cs.z, expf(l.w - cm.w)/cs.w };
    float4 cb  = { expf(l.x - rm)/rs, expf(l.y - rm)/rs,
                   expf(l.z - rm)/rs, expf(l.w - rm)/rs };
    *(float4*)(g_disp   + (size_t)t * SS + j) = dsp;
    *(float4*)(g_logits + (size_t)t * SS + j) = cb;
}

// ---------------- launch ----------------
extern "C" void kernel_launch(void* const* d_in, const int* in_sizes, int n_in,
                              void* d_out, int out_size) {
    const float* x     = (const float*)d_in[0];
    const int*   ca    = (const int*)  d_in[1];
    const float* phi   = (const float*)d_in[2];
    const float* scale = (const float*)d_in[3];
    const float* w1    = (const float*)d_in[4];
    const float* b1    = (const float*)d_in[5];
    const float* w2    = (const float*)d_in[6];
    const float* b2    = (const float*)d_in[7];
    float* out = (float*)d_out;

    const int Y_ELEMS = BB * MM * DD;
    float* mixo = nullptr; float* cluso = nullptr;
    if (out_size >= Y_ELEMS + 2 * TT * KK) {
        mixo  = out + Y_ELEMS;
        cluso = mixo + TT * KK;
    }

    // dynamic smem sizes (floats -> bytes)
    const int SM_KMAJ = STAGES * (16*136 + 16*136) * 4;   // MODE1
    const int SM_ROW  = STAGES * (128*20 + 16*136) * 4;   // MODE0,2,3,4
    cudaFuncSetAttribute(gemm_tc<0>, cudaFuncAttributeMaxDynamicSharedMemorySize, SM_ROW);
    cudaFuncSetAttribute(gemm_tc<1>, cudaFuncAttributeMaxDynamicSharedMemorySize, SM_KMAJ);
    cudaFuncSetAttribute(gemm_tc<2>, cudaFuncAttributeMaxDynamicSharedMemorySize, SM_ROW);
    cudaFuncSetAttribute(gemm_tc<3>, cudaFuncAttributeMaxDynamicSharedMemorySize, SM_ROW);
    cudaFuncSetAttribute(gemm_tc<4>, cudaFuncAttributeMaxDynamicSharedMemorySize, SM_ROW);

    k_phin<<<4, 256>>>(phi, scale);                   // 0 (also zeroes counts)
    k_norm_x<<<TT, 256>>>(x);                         // 1
    k_seg0<<<dim3(NG, 6), 128>>>(ca);                 // 2
    k_red_mean<<<96, 256>>>();                        // 3
    k_seg1<<<dim3(NG, 6), 128>>>(ca);                 // 4
    k_red_mad<<<96, 256>>>();                         // 5
    k_W<<<1, 1024>>>();                               // 6
    k_apply<<<TT, 256>>>(ca);                         // 7
    gemm_tc<0><<<dim3(8, 64), 256, SM_ROW>>>(nullptr, nullptr, nullptr, ca);   // logits

    k_topk<<<1024, 256>>>(mixo, cluso);               // + row softmax stats
    k_colstats<<<dim3(32, BB), 256>>>();
    k_dispcomb<<<TT, 256>>>();

    gemm_tc<1><<<dim3(6, 8, BB), 256, SM_KMAJ>>>(nullptr, nullptr, nullptr, ca); // xs
    gemm_tc<2><<<dim3(16, 2, NE), 256, SM_ROW>>>(w1, b1, nullptr, ca);           // h
    gemm_tc<3><<<dim3(6, 2, NE), 256, SM_ROW>>>(w2, b2, nullptr, ca);            // ys
    gemm_tc<4><<<dim3(6, 8, BB), 256, SM_ROW>>>(nullptr, nullptr, out, ca);      // y
}